// round 6
// baseline (speedup 1.0000x reference)
#include <cuda_runtime.h>
#include <math.h>
#include <stdint.h>

#define TT 34
#define NV 14
#define NROW (TT * NV)      // 476
#define RS 12               // row stride in floats

// -------- fast approx intrinsics -----
__device__ __forceinline__ float fexp2(float x) {
    float r; asm("ex2.approx.f32 %0, %1;" : "=f"(r) : "f"(x)); return r;
}
__device__ __forceinline__ float frsq(float x) {
    float r; asm("rsqrt.approx.f32 %0, %1;" : "=f"(r) : "f"(x)); return r;
}
__device__ __forceinline__ float frcp(float x) {
    float r; asm("rcp.approx.f32 %0, %1;" : "=f"(r) : "f"(x)); return r;
}

// ----------------------------------------------------------------------------
// Epilogue for one (b,t): full post-attention pipeline -> 14 logits into ob[].
// ----------------------------------------------------------------------------
__device__ __forceinline__ void do_epi(
    const float* __restrict__ sc, const float* __restrict__ sqx,
    float a0, float a1, float a2, float a3, float a4, float den,
    int row, float* __restrict__ ob)
{
    const float* qp = sqx + row * RS;
    float x0 = qp[4], x1 = qp[5], x2 = qp[6], x3 = qp[7], x4 = qp[9];
    float inv = frcp(den);
    float o0 = a0 * inv, o1 = a1 * inv, o2 = a2 * inv, o3 = a3 * inv, o4 = a4 * inv;

    float y0 = x0 + o0*sc[0]  + o1*sc[5]  + o2*sc[10] + o3*sc[15] + o4*sc[20];
    float y1 = x1 + o0*sc[1]  + o1*sc[6]  + o2*sc[11] + o3*sc[16] + o4*sc[21];
    float y2 = x2 + o0*sc[2]  + o1*sc[7]  + o2*sc[12] + o3*sc[17] + o4*sc[22];
    float y3 = x3 + o0*sc[3]  + o1*sc[8]  + o2*sc[13] + o3*sc[18] + o4*sc[23];
    float y4 = x4 + o0*sc[4]  + o1*sc[9]  + o2*sc[14] + o3*sc[19] + o4*sc[24];

    float r2 = frsq((y0*y0 + y1*y1 + y2*y2 + y3*y3 + y4*y4) * 0.2f + 1e-5f);

    float g0 = fmaf(r2, y0*sc[108] + y1*sc[109] + y2*sc[110] + y3*sc[111] + y4*sc[112], sc[118]);
    float g1 = fmaf(r2, y0*sc[113] + y1*sc[114] + y2*sc[115] + y3*sc[116] + y4*sc[117], sc[119]);

    const float isq2 = 0.70710678118654752f;
    float e0 = 0.5f * g0 * (1.0f + erff(g0 * isq2));
    float e1 = 0.5f * g1 * (1.0f + erff(g1 * isq2));

    float z0 = y0 + sc[130] + e0*sc[120] + e1*sc[121];
    float z1 = y1 + sc[131] + e0*sc[122] + e1*sc[123];
    float z2 = y2 + sc[132] + e0*sc[124] + e1*sc[125];
    float z3 = y3 + sc[133] + e0*sc[126] + e1*sc[127];
    float z4 = y4 + sc[134] + e0*sc[128] + e1*sc[129];

    float rf = frsq((z0*z0 + z1*z1 + z2*z2 + z3*z3 + z4*z4) * 0.2f + 1e-5f);
    z0 *= rf; z1 *= rf; z2 *= rf; z3 *= rf; z4 *= rf;

#pragma unroll
    for (int v = 0; v < NV; v++) {
        ob[v] = z0*sc[28 + v] + z1*sc[44 + v] + z2*sc[60 + v]
              + z3*sc[76 + v] + z4*sc[92 + v];
    }
}

// kv row layout: [k0,k1,k2,k3, v0,v1,v2,v3, k4, v4, -, -] (k pre-scaled log2e/sqrt5)
// tree-shaped dot: two parallel chains
#define ROW_UPDATE(j)                                                          \
    {                                                                          \
        float ua = fmaf(qr[j][1], kk.y, qr[j][0] * kk.x);                      \
        float ub = fmaf(qr[j][3], kk.w,                                        \
                   fmaf(qr[j][2], kk.z, qr[j][4] * kv4.x));                    \
        float e = fexp2(ua + ub);                                              \
        den[j] += e;                                                           \
        acc[j][0] = fmaf(e, vv.x, acc[j][0]);                                  \
        acc[j][1] = fmaf(e, vv.y, acc[j][1]);                                  \
        acc[j][2] = fmaf(e, vv.z, acc[j][2]);                                  \
        acc[j][3] = fmaf(e, vv.w, acc[j][3]);                                  \
        acc[j][4] = fmaf(e, kv4.y, acc[j][4]);                                 \
    }

#define LOAD_ROW(sidx, c)                                                      \
    const float* kvp = s_kv + (((sidx) * NV) + (c)) * RS;                      \
    float4 kk  = *reinterpret_cast<const float4*>(kvp);                        \
    float4 vv  = *reinterpret_cast<const float4*>(kvp + 4);                    \
    float2 kv4 = *reinterpret_cast<const float2*>(kvp + 8);

__global__ __launch_bounds__(256, 2) void micro_tf_kernel(
    const int*   __restrict__ idx,
    const float* __restrict__ tok_emb,
    const float* __restrict__ p_amp,   const float* __restrict__ p_phase,
    const float* __restrict__ p_slope, const float* __restrict__ p_offset,
    const float* __restrict__ p_cs,    const float* __restrict__ p_ci,
    const float* __restrict__ z_hi,    const float* __restrict__ special,
    const float* __restrict__ q_w,     const float* __restrict__ v_w,
    const float* __restrict__ out_A,   const float* __restrict__ out_B,
    const float* __restrict__ q_phase,
    const float* __restrict__ ln1_w,   const float* __restrict__ ln2_w,
    const float* __restrict__ lnf_w,
    const float* __restrict__ fc1_w,   const float* __restrict__ fc1_b,
    const float* __restrict__ fc2_w,   const float* __restrict__ fc2_b,
    const float* __restrict__ head_w,
    float* __restrict__ out, int B)
{
    __shared__ __align__(16) float s_kv[NROW * RS];
    __shared__ __align__(16) float s_qx[NROW * RS];
    __shared__ float s_c[144];

    const int tid = threadIdx.x;

    // ---------------- per-CTA table build ----------------
    for (int r = tid; r < NROW; r += 256) {
        int t = r / NV, a = r % NV;
        float p0, p1, p2;
        if (t == 33)      { p0 = 0.f;        p1 = 0.f;        p2 = 0.f; }
        else if (t == 32) { p0 = z_hi[0];    p1 = z_hi[1];    p2 = z_hi[2]; }
        else if (t == 10) { p0 = special[0]; p1 = special[1]; p2 = special[2]; }
        else if (t == 21) { p0 = special[3]; p1 = special[4]; p2 = special[5]; }
        else {
            int i = (t < 10) ? t : ((t < 21) ? t - 11 : t - 22);
            float fi  = (float)i;
            float ang = 0.62831853071795864f * fi + p_phase[0];
            float amp = p_amp[0];
            float b0 = amp * cosf(ang);
            float b1 = amp * sinf(ang);
            float b2 = p_slope[0] * fi + p_offset[0];
            float m  = 1.0f + p_ci[0] + p_cs[0] * fi;
            p0 = b0 * m; p1 = b1 * m; p2 = b2 * m;
        }
        float x0 = tok_emb[a * 2], x1 = tok_emb[a * 2 + 1];
        float ms = (x0*x0 + x1*x1 + p0*p0 + p1*p1 + p2*p2) * 0.2f;
        float rr = rsqrtf(ms + 1e-5f);
        float h0 = x0*rr*ln1_w[0], h1 = x1*rr*ln1_w[1];
        float h2 = p0*rr*ln1_w[2], h3 = p1*rr*ln1_w[3], h4 = p2*rr*ln1_w[4];

        float q[5], v[5];
#pragma unroll
        for (int d = 0; d < 5; d++)
            q[d] = h2*q_w[d*3] + h3*q_w[d*3+1] + h4*q_w[d*3+2];
#pragma unroll
        for (int d = 0; d < 5; d++)
            v[d] = h0*v_w[d*2] + h1*v_w[d*2+1];

        float cc = cosf(q_phase[0]), ss = sinf(q_phase[0]);
        float qr0 = q[0]*cc - q[1]*ss, qr1 = q[0]*ss + q[1]*cc;
        float qr2 = q[2]*cc - q[3]*ss, qr3 = q[2]*ss + q[3]*cc;

        const float ksc = 1.4426950408889634f * 0.44721359549995794f; // log2(e)/sqrt(5)
        float* kvp = s_kv + r * RS;
        kvp[0] = q[0]*ksc; kvp[1] = q[1]*ksc; kvp[2] = q[2]*ksc; kvp[3] = q[3]*ksc;
        kvp[4] = v[0]; kvp[5] = v[1]; kvp[6] = v[2]; kvp[7] = v[3];
        kvp[8] = q[4]*ksc; kvp[9] = v[4]; kvp[10] = 0.f; kvp[11] = 0.f;

        float* qxp = s_qx + r * RS;
        qxp[0] = qr0; qxp[1] = qr1; qxp[2] = qr2; qxp[3] = qr3;
        qxp[4] = x0;  qxp[5] = x1;  qxp[6] = p0;  qxp[7] = p1;
        qxp[8] = q[4]; qxp[9] = p2; qxp[10] = 0.f; qxp[11] = 0.f;
    }

    if (tid == 0) {
        for (int d = 0; d < 5; d++)
            for (int j = 0; j < 5; j++)
                s_c[d*5 + j] = out_A[d*2]*out_B[j] + out_A[d*2+1]*out_B[5+j];
        for (int j = 0; j < 5; j++)
            for (int v = 0; v < NV; v++)
                s_c[28 + j*16 + v] =
                    lnf_w[j] * (head_w[j]*tok_emb[v*2] + head_w[5+j]*tok_emb[v*2+1]);
        for (int f = 0; f < 2; f++)
            for (int j = 0; j < 5; j++)
                s_c[108 + f*5 + j] = fc1_w[f*5 + j] * ln2_w[j];
        s_c[118] = fc1_b[0]; s_c[119] = fc1_b[1];
        for (int d = 0; d < 5; d++) {
            s_c[120 + d*2]     = fc2_w[d*2];
            s_c[120 + d*2 + 1] = fc2_w[d*2 + 1];
            s_c[130 + d]       = fc2_b[d];
        }
    }
    __syncthreads();

    const int b = blockIdx.x * 256 + tid;
    if (b >= B) return;

    // ---------------- pack this row's 34 tokens, 4 bits each ----------------
    uint32_t pk[5] = {0u, 0u, 0u, 0u, 0u};
    const int2* ip2 = reinterpret_cast<const int2*>(idx + (size_t)b * TT);
#pragma unroll
    for (int w = 0; w < 17; w++) {
        int2 tv = __ldg(ip2 + w);
        const int s0 = 2*w, s1 = 2*w + 1;
        pk[s0 >> 3] |= ((uint32_t)tv.x) << ((s0 & 7) * 4);
        pk[s1 >> 3] |= ((uint32_t)tv.y) << ((s1 & 7) * 4);
    }

    float* obase = out + (size_t)b * (TT * NV);

    float qr[8][5], acc[8][5], den[8];
    float obuf[28];

#pragma unroll
    for (int k = 0; k < 5; k++) {
        const int nt = (k == 4) ? 2 : 8;
        const uint32_t tb = pk[k];

        // load q_rot rows for this tile, zero accumulators
#pragma unroll
        for (int j = 0; j < 8; j++) {
            if (j < nt) {
                int a = (tb >> (4*j)) & 15;
                const float* qp = s_qx + (((8*k + j) * NV) + a) * RS;
                float4 qq = *reinterpret_cast<const float4*>(qp);
                qr[j][0] = qq.x; qr[j][1] = qq.y; qr[j][2] = qq.z; qr[j][3] = qq.w;
                qr[j][4] = qp[8];
                den[j] = 0.f;
                acc[j][0] = acc[j][1] = acc[j][2] = acc[j][3] = acc[j][4] = 0.f;
            }
        }

        // phase 1: full octets s in [0, 8k)  — unroll 2 rows in flight
#pragma unroll
        for (int w = 0; w < k; w++) {
            uint32_t bits = pk[w];
#pragma unroll 2
            for (int jj = 0; jj < 8; jj++) {
                int c = bits & 15; bits >>= 4;
                LOAD_ROW(w*8 + jj, c)
#pragma unroll
                for (int j = 0; j < 8; j++) if (j < nt) ROW_UPDATE(j);
            }
        }

        // phase 2: triangular, s = 8k + s2  (query j active iff j >= s2)
        {
            uint32_t bits = tb;
#pragma unroll
            for (int s2 = 0; s2 < 8; s2++) {
                if (s2 < nt) {
                    int c = bits & 15;
                    LOAD_ROW(8*k + s2, c)
#pragma unroll
                    for (int j = 0; j < 8; j++) if (j >= s2 && j < nt) ROW_UPDATE(j);
                }
                bits >>= 4;
            }
        }

        // epilogue per pair of t's, 112B contiguous flush
#pragma unroll
        for (int jp = 0; jp < 4; jp++) {
            const int j0 = 2*jp, j1 = 2*jp + 1;
            if (j0 < nt) {
                int t0 = 8*k + j0, t1 = 8*k + j1;
                int a0 = (tb >> (4*j0)) & 15;
                int a1 = (tb >> (4*j1)) & 15;
                do_epi(s_c, s_qx, acc[j0][0], acc[j0][1], acc[j0][2], acc[j0][3],
                       acc[j0][4], den[j0], t0 * NV + a0, obuf);
                do_epi(s_c, s_qx, acc[j1][0], acc[j1][1], acc[j1][2], acc[j1][3],
                       acc[j1][4], den[j1], t1 * NV + a1, obuf + 14);
                float4* dst = reinterpret_cast<float4*>(obase + t0 * NV);
#pragma unroll
                for (int i = 0; i < 7; i++)
                    dst[i] = make_float4(obuf[4*i], obuf[4*i+1], obuf[4*i+2], obuf[4*i+3]);
            }
        }
    }
}

extern "C" void kernel_launch(void* const* d_in, const int* in_sizes, int n_in,
                              void* d_out, int out_size)
{
    const int*   idx     = (const int*)  d_in[0];
    const float* tok_emb = (const float*)d_in[1];
    const float* amp     = (const float*)d_in[2];
    const float* phase   = (const float*)d_in[3];
    const float* slope   = (const float*)d_in[4];
    const float* offset  = (const float*)d_in[5];
    const float* cslope  = (const float*)d_in[6];
    const float* cicept  = (const float*)d_in[7];
    const float* z_hi    = (const float*)d_in[8];
    const float* special = (const float*)d_in[9];
    const float* q_w     = (const float*)d_in[10];
    const float* v_w     = (const float*)d_in[11];
    const float* out_A   = (const float*)d_in[12];
    const float* out_B   = (const float*)d_in[13];
    const float* q_phase = (const float*)d_in[14];
    const float* ln1_w   = (const float*)d_in[15];
    const float* ln2_w   = (const float*)d_in[16];
    const float* lnf_w   = (const float*)d_in[17];
    const float* fc1_w   = (const float*)d_in[18];
    const float* fc1_b   = (const float*)d_in[19];
    const float* fc2_w   = (const float*)d_in[20];
    const float* fc2_b   = (const float*)d_in[21];
    const float* head_w  = (const float*)d_in[22];
    float* out = (float*)d_out;

    const int B = in_sizes[0] / TT;
    dim3 grid((B + 255) / 256);
    micro_tf_kernel<<<grid, 256>>>(
        idx, tok_emb, amp, phase, slope, offset, cslope, cicept,
        z_hi, special, q_w, v_w, out_A, out_B, q_phase,
        ln1_w, ln2_w, lnf_w, fc1_w, fc1_b, fc2_w, fc2_b, head_w,
        out, B);
}

// round 7
// speedup vs baseline: 1.8670x; 1.8670x over previous
#include <cuda_runtime.h>
#include <math.h>
#include <stdint.h>

#define TT 34
#define NV 14
#define NROW (TT * NV)      // 476
#define RS 12               // row stride (floats) for both tables

// -------- fast approx intrinsics (accuracy ~1e-6 rel, fine vs 1e-3 tol) -----
__device__ __forceinline__ float fexp2(float x) {
    float r; asm("ex2.approx.f32 %0, %1;" : "=f"(r) : "f"(x)); return r;
}
__device__ __forceinline__ float frsq(float x) {
    float r; asm("rsqrt.approx.f32 %0, %1;" : "=f"(r) : "f"(x)); return r;
}
__device__ __forceinline__ float frcp(float x) {
    float r; asm("rcp.approx.f32 %0, %1;" : "=f"(r) : "f"(x)); return r;
}

// ----------------------------------------------------------------------------
// Epilogue for ONE t: computes 14 logits into ob[0..13]. Called from the
// noinline pair wrapper below — keeps mainloop register pressure isolated.
// ----------------------------------------------------------------------------
__device__ __forceinline__ void epi_one(
    const float* __restrict__ sc, const float* __restrict__ sqx,
    float a0, float a1, float a2, float a3, float a4, float den,
    int row, float* __restrict__ ob)
{
    const float* qp = sqx + row * RS;
    float x0 = qp[4], x1 = qp[5], x2 = qp[6], x3 = qp[7], x4 = qp[9];
    float inv = frcp(den);
    float o0 = a0 * inv, o1 = a1 * inv, o2 = a2 * inv, o3 = a3 * inv, o4 = a4 * inv;

    // residual + out @ M1
    float y0 = x0 + o0*sc[0]  + o1*sc[5]  + o2*sc[10] + o3*sc[15] + o4*sc[20];
    float y1 = x1 + o0*sc[1]  + o1*sc[6]  + o2*sc[11] + o3*sc[16] + o4*sc[21];
    float y2 = x2 + o0*sc[2]  + o1*sc[7]  + o2*sc[12] + o3*sc[17] + o4*sc[22];
    float y3 = x3 + o0*sc[3]  + o1*sc[8]  + o2*sc[13] + o3*sc[18] + o4*sc[23];
    float y4 = x4 + o0*sc[4]  + o1*sc[9]  + o2*sc[14] + o3*sc[19] + o4*sc[24];

    float r2 = frsq((y0*y0 + y1*y1 + y2*y2 + y3*y3 + y4*y4) * 0.2f + 1e-5f);

    float g0 = fmaf(r2, y0*sc[108] + y1*sc[109] + y2*sc[110] + y3*sc[111] + y4*sc[112], sc[118]);
    float g1 = fmaf(r2, y0*sc[113] + y1*sc[114] + y2*sc[115] + y3*sc[116] + y4*sc[117], sc[119]);

    const float isq2 = 0.70710678118654752f;
    float e0 = 0.5f * g0 * (1.0f + erff(g0 * isq2));
    float e1 = 0.5f * g1 * (1.0f + erff(g1 * isq2));

    float z0 = y0 + sc[130] + e0*sc[120] + e1*sc[121];
    float z1 = y1 + sc[131] + e0*sc[122] + e1*sc[123];
    float z2 = y2 + sc[132] + e0*sc[124] + e1*sc[125];
    float z3 = y3 + sc[133] + e0*sc[126] + e1*sc[127];
    float z4 = y4 + sc[134] + e0*sc[128] + e1*sc[129];

    float rf = frsq((z0*z0 + z1*z1 + z2*z2 + z3*z3 + z4*z4) * 0.2f + 1e-5f);
    z0 *= rf; z1 *= rf; z2 *= rf; z3 *= rf; z4 *= rf;

#pragma unroll
    for (int v = 0; v < NV; v++) {
        ob[v] = z0*sc[28 + v] + z1*sc[44 + v] + z2*sc[60 + v]
              + z3*sc[76 + v] + z4*sc[92 + v];
    }
}

// Pair epilogue: two consecutive t's -> 28 contiguous floats -> 7x STG.128.
__device__ __noinline__ void do_epilogue_pair(
    const float* __restrict__ sc, const float* __restrict__ sqx,
    float b00, float b01, float b02, float b03, float b04, float bd0, int row0,
    float b10, float b11, float b12, float b13, float b14, float bd1, int row1,
    float* __restrict__ op)
{
    float ob[28];
    epi_one(sc, sqx, b00, b01, b02, b03, b04, bd0, row0, ob);
    epi_one(sc, sqx, b10, b11, b12, b13, b14, bd1, row1, ob + 14);
    float4* dst = reinterpret_cast<float4*>(op);
#pragma unroll
    for (int i = 0; i < 7; i++)
        dst[i] = make_float4(ob[4*i], ob[4*i+1], ob[4*i+2], ob[4*i+3]);
}

#define PAIR_UPDATE(j)                                                         \
    {                                                                          \
        float l = fmaf(qr[j][0], kk.x,                                         \
                  fmaf(qr[j][1], kk.y,                                         \
                  fmaf(qr[j][2], kk.z,                                         \
                  fmaf(qr[j][3], kk.w, qr[j][4] * k4))));                      \
        float e = fexp2(l);                                                    \
        den[j] += e;                                                           \
        acc[j][0] = fmaf(e, vv.x, acc[j][0]);                                  \
        acc[j][1] = fmaf(e, vv.y, acc[j][1]);                                  \
        acc[j][2] = fmaf(e, vv.z, acc[j][2]);                                  \
        acc[j][3] = fmaf(e, vv.w, acc[j][3]);                                  \
        acc[j][4] = fmaf(e, v4,   acc[j][4]);                                  \
    }

__global__ __launch_bounds__(256, 2) void micro_tf_kernel(
    const int*   __restrict__ idx,
    const float* __restrict__ tok_emb,
    const float* __restrict__ p_amp,   const float* __restrict__ p_phase,
    const float* __restrict__ p_slope, const float* __restrict__ p_offset,
    const float* __restrict__ p_cs,    const float* __restrict__ p_ci,
    const float* __restrict__ z_hi,    const float* __restrict__ special,
    const float* __restrict__ q_w,     const float* __restrict__ v_w,
    const float* __restrict__ out_A,   const float* __restrict__ out_B,
    const float* __restrict__ q_phase,
    const float* __restrict__ ln1_w,   const float* __restrict__ ln2_w,
    const float* __restrict__ lnf_w,
    const float* __restrict__ fc1_w,   const float* __restrict__ fc1_b,
    const float* __restrict__ fc2_w,   const float* __restrict__ fc2_b,
    const float* __restrict__ head_w,
    float* __restrict__ out, int B)
{
    __shared__ __align__(16) float s_kv[NROW * RS];   // [k0..k3, v0..v3, k4, v4, -, -]
    __shared__ __align__(16) float s_qx[NROW * RS];   // [qr0..qr3, x0, x1, p0, p1, qr4, p2, -, -]
    __shared__ float s_c[144];

    const int tid = threadIdx.x;

    // ---------------- per-CTA table build (tiny) ----------------
    for (int r = tid; r < NROW; r += 256) {
        int t = r / NV, a = r % NV;
        float p0, p1, p2;
        if (t == 33)      { p0 = 0.f;        p1 = 0.f;        p2 = 0.f; }
        else if (t == 32) { p0 = z_hi[0];    p1 = z_hi[1];    p2 = z_hi[2]; }
        else if (t == 10) { p0 = special[0]; p1 = special[1]; p2 = special[2]; }
        else if (t == 21) { p0 = special[3]; p1 = special[4]; p2 = special[5]; }
        else {
            int i = (t < 10) ? t : ((t < 21) ? t - 11 : t - 22);
            float fi  = (float)i;
            float ang = 0.62831853071795864f * fi + p_phase[0];  // 2*pi/10 * i + phase
            float amp = p_amp[0];
            float b0 = amp * cosf(ang);
            float b1 = amp * sinf(ang);
            float b2 = p_slope[0] * fi + p_offset[0];
            float m  = 1.0f + p_ci[0] + p_cs[0] * fi;
            p0 = b0 * m; p1 = b1 * m; p2 = b2 * m;
        }
        float x0 = tok_emb[a * 2], x1 = tok_emb[a * 2 + 1];
        float ms = (x0*x0 + x1*x1 + p0*p0 + p1*p1 + p2*p2) * 0.2f;
        float rr = rsqrtf(ms + 1e-5f);
        float h0 = x0*rr*ln1_w[0], h1 = x1*rr*ln1_w[1];
        float h2 = p0*rr*ln1_w[2], h3 = p1*rr*ln1_w[3], h4 = p2*rr*ln1_w[4];

        float q[5], v[5];
#pragma unroll
        for (int d = 0; d < 5; d++)
            q[d] = h2*q_w[d*3] + h3*q_w[d*3+1] + h4*q_w[d*3+2];
#pragma unroll
        for (int d = 0; d < 5; d++)
            v[d] = h0*v_w[d*2] + h1*v_w[d*2+1];

        float cc = cosf(q_phase[0]), ss = sinf(q_phase[0]);
        float qr0 = q[0]*cc - q[1]*ss, qr1 = q[0]*ss + q[1]*cc;
        float qr2 = q[2]*cc - q[3]*ss, qr3 = q[2]*ss + q[3]*cc;

        const float ksc = 1.4426950408889634f * 0.44721359549995794f; // log2(e)/sqrt(5)
        float* kvp = s_kv + r * RS;
        kvp[0] = q[0]*ksc; kvp[1] = q[1]*ksc; kvp[2] = q[2]*ksc; kvp[3] = q[3]*ksc;
        kvp[4] = v[0]; kvp[5] = v[1]; kvp[6] = v[2]; kvp[7] = v[3];
        kvp[8] = q[4]*ksc; kvp[9] = v[4]; kvp[10] = 0.f; kvp[11] = 0.f;

        float* qxp = s_qx + r * RS;
        qxp[0] = qr0; qxp[1] = qr1; qxp[2] = qr2; qxp[3] = qr3;
        qxp[4] = x0;  qxp[5] = x1;  qxp[6] = p0;  qxp[7] = p1;
        qxp[8] = q[4]; qxp[9] = p2; qxp[10] = 0.f; qxp[11] = 0.f;
    }

    if (tid == 0) {
        for (int d = 0; d < 5; d++)
            for (int j = 0; j < 5; j++)
                s_c[d*5 + j] = out_A[d*2]*out_B[j] + out_A[d*2+1]*out_B[5+j];
        for (int j = 0; j < 5; j++)
            for (int v = 0; v < NV; v++)
                s_c[28 + j*16 + v] =
                    lnf_w[j] * (head_w[j]*tok_emb[v*2] + head_w[5+j]*tok_emb[v*2+1]);
        for (int f = 0; f < 2; f++)
            for (int j = 0; j < 5; j++)
                s_c[108 + f*5 + j] = fc1_w[f*5 + j] * ln2_w[j];
        s_c[118] = fc1_b[0]; s_c[119] = fc1_b[1];
        for (int d = 0; d < 5; d++) {
            s_c[120 + d*2]     = fc2_w[d*2];
            s_c[120 + d*2 + 1] = fc2_w[d*2 + 1];
            s_c[130 + d]       = fc2_b[d];
        }
    }
    __syncthreads();

    const int b = blockIdx.x * 256 + tid;
    if (b >= B) return;

    // ---------------- load and 4-bit-pack this row's 34 tokens ----------------
    uint32_t pk[5] = {0u, 0u, 0u, 0u, 0u};
    const int2* ip2 = reinterpret_cast<const int2*>(idx + (size_t)b * TT);
#pragma unroll
    for (int w = 0; w < 17; w++) {
        int2 tv = __ldg(ip2 + w);
        const int s0 = 2*w, s1 = 2*w + 1;
        pk[s0 >> 3] |= ((uint32_t)tv.x) << ((s0 & 7) * 4);
        pk[s1 >> 3] |= ((uint32_t)tv.y) << ((s1 & 7) * 4);
    }

    float* obase = out + (size_t)b * (TT * NV);

    float qr[8][5], acc[8][5], den[8];

#pragma unroll
    for (int k = 0; k < 5; k++) {
        const int nt = (k == 4) ? 2 : 8;
        const uint32_t tb = pk[k];

        // load q_rot rows for this tile, zero accumulators
#pragma unroll
        for (int j = 0; j < 8; j++) {
            if (j < nt) {
                int a = (tb >> (4*j)) & 15;
                const float* qp = s_qx + (((8*k + j) * NV) + a) * RS;
                float4 qq = *reinterpret_cast<const float4*>(qp);
                qr[j][0] = qq.x; qr[j][1] = qq.y; qr[j][2] = qq.z; qr[j][3] = qq.w;
                qr[j][4] = qp[8];
                den[j] = 0.f;
                acc[j][0] = acc[j][1] = acc[j][2] = acc[j][3] = acc[j][4] = 0.f;
            }
        }

        // phase 1: full octets s in [0, 8k)
#pragma unroll
        for (int w = 0; w < k; w++) {
            uint32_t bits = pk[w];
#pragma unroll 1
            for (int jj = 0; jj < 8; jj++) {
                int c = bits & 15; bits >>= 4;
                const float* kvp = s_kv + (((w*8 + jj) * NV) + c) * RS;
                float4 kk = *reinterpret_cast<const float4*>(kvp);
                float4 vv = *reinterpret_cast<const float4*>(kvp + 4);
                float k4 = kvp[8], v4 = kvp[9];
#pragma unroll
                for (int j = 0; j < 8; j++) if (j < nt) PAIR_UPDATE(j);
            }
        }

        // phase 2: triangular part, s = 8k + s2
        {
            uint32_t bits = tb;
#pragma unroll
            for (int s2 = 0; s2 < 8; s2++) {
                if (s2 < nt) {
                    int c = bits & 15;
                    const float* kvp = s_kv + (((8*k + s2) * NV) + c) * RS;
                    float4 kk = *reinterpret_cast<const float4*>(kvp);
                    float4 vv = *reinterpret_cast<const float4*>(kvp + 4);
                    float k4 = kvp[8], v4 = kvp[9];
#pragma unroll
                    for (int j = 0; j < 8; j++) if (j >= s2 && j < nt) PAIR_UPDATE(j);
                }
                bits >>= 4;
            }
        }

        // epilogue per pair of t's (noinline) -> 7x STG.128 per pair
#pragma unroll
        for (int jp = 0; jp < 4; jp++) {
            const int j0 = 2*jp, j1 = 2*jp + 1;
            if (j0 < nt) {
                int t0 = 8*k + j0, t1 = 8*k + j1;
                int a0 = (tb >> (4*j0)) & 15;
                int a1 = (tb >> (4*j1)) & 15;
                do_epilogue_pair(s_c, s_qx,
                    acc[j0][0], acc[j0][1], acc[j0][2], acc[j0][3], acc[j0][4],
                    den[j0], t0 * NV + a0,
                    acc[j1][0], acc[j1][1], acc[j1][2], acc[j1][3], acc[j1][4],
                    den[j1], t1 * NV + a1,
                    obase + t0 * NV);
            }
        }
    }
}

extern "C" void kernel_launch(void* const* d_in, const int* in_sizes, int n_in,
                              void* d_out, int out_size)
{
    const int*   idx     = (const int*)  d_in[0];
    const float* tok_emb = (const float*)d_in[1];
    const float* amp     = (const float*)d_in[2];
    const float* phase   = (const float*)d_in[3];
    const float* slope   = (const float*)d_in[4];
    const float* offset  = (const float*)d_in[5];
    const float* cslope  = (const float*)d_in[6];
    const float* cicept  = (const float*)d_in[7];
    const float* z_hi    = (const float*)d_in[8];
    const float* special = (const float*)d_in[9];
    const float* q_w     = (const float*)d_in[10];
    const float* v_w     = (const float*)d_in[11];
    const float* out_A   = (const float*)d_in[12];
    const float* out_B   = (const float*)d_in[13];
    const float* q_phase = (const float*)d_in[14];
    const float* ln1_w   = (const float*)d_in[15];
    const float* ln2_w   = (const float*)d_in[16];
    const float* lnf_w   = (const float*)d_in[17];
    const float* fc1_w   = (const float*)d_in[18];
    const float* fc1_b   = (const float*)d_in[19];
    const float* fc2_w   = (const float*)d_in[20];
    const float* fc2_b   = (const float*)d_in[21];
    const float* head_w  = (const float*)d_in[22];
    float* out = (float*)d_out;

    const int B = in_sizes[0] / TT;
    dim3 grid((B + 255) / 256);
    micro_tf_kernel<<<grid, 256>>>(
        idx, tok_emb, amp, phase, slope, offset, cslope, cicept,
        z_hi, special, q_w, v_w, out_A, out_B, q_phase,
        ln1_w, ln2_w, lnf_w, fc1_w, fc1_b, fc2_w, fc2_b, head_w,
        out, B);
}